// round 2
// baseline (speedup 1.0000x reference)
#include <cuda_runtime.h>

#define FULLMASK 0xffffffffu

constexpr int NMAX = 50000;
constexpr int EMAX = 850000;   // 800000 edges + 50000 self loops
constexpr int HDIM = 32;

// ---------------- scratch (device globals; no allocation) ----------------
__device__ float g_hpA[NMAX * HDIM];
__device__ float g_hpB[NMAX * HDIM];
__device__ float g_plbuf[2][NMAX];
__device__ float g_prbuf[2][NMAX];
__device__ int   g_deg[NMAX];
__device__ int   g_rowptr[NMAX + 1];
__device__ int   g_cursor[NMAX];
__device__ int   g_col[EMAX];
__device__ int   g_bsum[512];

// ---------------- fast math (no MUFU) ----------------
// exp(x) for x <= 0 (clamped at -87). ~10 FMA/ALU ops, rel err ~1e-7.
__device__ __forceinline__ float fexp(float x) {
    x = fmaxf(x, -87.0f);
    float t = x * 1.4426950408889634f;       // log2(e)
    float r2 = t + 12582912.0f;              // round-to-nearest via magic number
    int   n  = __float_as_int(r2) - 0x4B400000;
    float f  = t - (r2 - 12582912.0f);       // f in [-0.5, 0.5]
    float p  = 1.5398530e-4f;
    p = fmaf(p, f, 1.3333558e-3f);
    p = fmaf(p, f, 9.6181291e-3f);
    p = fmaf(p, f, 5.5504109e-2f);
    p = fmaf(p, f, 2.4022651e-1f);
    p = fmaf(p, f, 6.9314718e-1f);
    p = fmaf(p, f, 1.0f);
    float s = __int_as_float((n + 127) << 23);
    return p * s;
}

// 1/(1+e) for e in [0,1]  (denominator d in (1,2]).
// Minimax linear seed for 1/d on [1,2]: 24/17 - 8/17*d (max rel err 1/17),
// then two Newton iterations -> rel err ~1.2e-5. Seed stays in (0, 2/d): converges.
__device__ __forceinline__ float rcp1p(float e) {
    float d = 1.0f + e;
    float y = fmaf(d, -0.47058824f, 1.41176471f);  // 24/17 - 8/17*d
    y = y * fmaf(-d, y, 2.0f);
    y = y * fmaf(-d, y, 2.0f);
    return y;
}

// ---------------- CSR build ----------------
__global__ void k_deg_init(int N) {
    int i = blockIdx.x * blockDim.x + threadIdx.x;
    if (i < N) g_deg[i] = 1;                 // self loop
}

__global__ void k_deg_count(const int* __restrict__ ei, int E) {
    int e = blockIdx.x * blockDim.x + threadIdx.x;
    if (e < E) atomicAdd(&g_deg[ei[E + e]], 1);
}

__global__ void k_scan1(int N) {
    __shared__ int sm[512];
    int i = blockIdx.x * 512 + threadIdx.x;
    int v = (i < N) ? g_deg[i] : 0;
    sm[threadIdx.x] = v;
    __syncthreads();
    #pragma unroll
    for (int off = 1; off < 512; off <<= 1) {
        int t = (threadIdx.x >= off) ? sm[threadIdx.x - off] : 0;
        __syncthreads();
        sm[threadIdx.x] += t;
        __syncthreads();
    }
    if (i < N) g_cursor[i] = sm[threadIdx.x];            // inclusive scan (temp)
    if (threadIdx.x == 511) g_bsum[blockIdx.x] = sm[511];
}

__global__ void k_scan2(int nb) {
    __shared__ int sm[512];
    if (threadIdx.x < nb) sm[threadIdx.x] = g_bsum[threadIdx.x];
    __syncthreads();
    if (threadIdx.x == 0) {
        int run = 0;
        for (int b = 0; b < nb; b++) { int t = sm[b]; sm[b] = run; run += t; }
    }
    __syncthreads();
    if (threadIdx.x < nb) g_bsum[threadIdx.x] = sm[threadIdx.x];
}

__global__ void k_scan3(int N) {
    int i = blockIdx.x * 512 + threadIdx.x;
    if (i < N) {
        int incl = g_cursor[i] + g_bsum[blockIdx.x];
        int excl = incl - g_deg[i];
        g_rowptr[i] = excl;
        g_cursor[i] = excl;
        if (i == N - 1) g_rowptr[N] = incl;
    }
}

__global__ void k_scatter(const int* __restrict__ ei, int E, int N) {
    int e = blockIdx.x * blockDim.x + threadIdx.x;
    if (e >= E + N) return;
    int s, d;
    if (e < E) { s = ei[e]; d = ei[E + e]; }
    else       { s = e - E; d = s; }
    int pos = atomicAdd(&g_cursor[d], 1);
    g_col[pos] = s;
}

// Sort each CSR segment (deterministic neighbor order -> deterministic output).
__global__ void k_sort(int N) {
    int i = blockIdx.x * blockDim.x + threadIdx.x;
    if (i >= N) return;
    int beg = g_rowptr[i], n = g_rowptr[i + 1] - beg;
    if (n <= 1) return;
    if (n <= 64) {
        int buf[64];
        for (int j = 0; j < n; j++) buf[j] = g_col[beg + j];
        for (int a = 1; a < n; a++) {
            int key = buf[a], b = a - 1;
            while (b >= 0 && buf[b] > key) { buf[b + 1] = buf[b]; b--; }
            buf[b + 1] = key;
        }
        for (int j = 0; j < n; j++) g_col[beg + j] = buf[j];
    } else {
        for (int a = 1; a < n; a++) {
            int key = g_col[beg + a], b = a - 1;
            while (b >= 0 && g_col[beg + b] > key) { g_col[beg + b + 1] = g_col[beg + b]; b--; }
            g_col[beg + b + 1] = key;
        }
    }
}

// ---------------- input layer: h0 = x@W0 + b0; hp0 = h0@Ws[0]; pl/pr ----------------
__global__ void __launch_bounds__(256) k_in(
    const float* __restrict__ x, const float* __restrict__ W0, const float* __restrict__ b0,
    const float* __restrict__ Ws0, const float* __restrict__ al0, const float* __restrict__ ar0,
    int N)
{
    __shared__ float W0s[128 * HDIM];
    __shared__ float b0s[HDIM];
    __shared__ float Wns[HDIM * HDIM];
    __shared__ float als[HDIM], ars[HDIM];
    int tid = threadIdx.x;
    for (int j = tid; j < 128 * HDIM; j += blockDim.x) W0s[j] = W0[j];
    for (int j = tid; j < HDIM * HDIM; j += blockDim.x) Wns[j] = Ws0[j];
    if (tid < HDIM) { b0s[tid] = b0[tid]; als[tid] = al0[tid]; ars[tid] = ar0[tid]; }
    __syncthreads();

    int lane = tid & 31;
    int wg = (blockIdx.x * blockDim.x + tid) >> 5;
    int nw = (gridDim.x * blockDim.x) >> 5;
    for (int i = wg; i < N; i += nw) {
        float xv[4];
        #pragma unroll
        for (int j = 0; j < 4; j++) xv[j] = x[i * 128 + j * 32 + lane];
        float h = 0.0f;
        #pragma unroll
        for (int k = 0; k < 128; k++) {
            float xk = __shfl_sync(FULLMASK, xv[k >> 5], k & 31);
            h = fmaf(xk, W0s[k * HDIM + lane], h);
        }
        h += b0s[lane];                                   // conv0 (no relu)
        // hp0 = h @ Ws[0]
        float hv = 0.0f;
        #pragma unroll
        for (int k = 0; k < HDIM; k++) {
            float hk = __shfl_sync(FULLMASK, h, k);
            hv = fmaf(hk, Wns[k * HDIM + lane], hv);
        }
        g_hpA[i * HDIM + lane] = hv;
        float t1 = hv * als[lane], t2 = hv * ars[lane];
        #pragma unroll
        for (int off = 16; off; off >>= 1) {
            t1 += __shfl_xor_sync(FULLMASK, t1, off);
            t2 += __shfl_xor_sync(FULLMASK, t2, off);
        }
        if (lane == 0) { g_plbuf[0][i] = t1; g_prbuf[0][i] = t2; }
    }
}

// ---------------- edge layer: softmax attention + aggregation + fused next GEMM ----------------
__global__ void __launch_bounds__(256) k_edge(
    int pp,                                      // 0: read A write B, 1: read B write A
    const float* __restrict__ bcur,              // bias of current layer [32]
    const float* __restrict__ Wnext,             // next layer W [32x32] (if !last)
    const float* __restrict__ alnext, const float* __restrict__ arnext,
    const float* __restrict__ W16, const float* __restrict__ b16,  // if last
    float* __restrict__ out16,
    int N, int last)
{
    __shared__ float tile[8][32 * 36];           // per-warp staged hj rows (stride 36: conflict-free)
    __shared__ float Wns[HDIM * HDIM];
    __shared__ float W16s[HDIM * 16];
    __shared__ float als[HDIM], ars[HDIM], bsm[HDIM];
    __shared__ float b16s[16];

    int tid = threadIdx.x;
    if (!last) {
        for (int j = tid; j < HDIM * HDIM; j += blockDim.x) Wns[j] = Wnext[j];
        if (tid < HDIM) { als[tid] = alnext[tid]; ars[tid] = arnext[tid]; }
    } else {
        for (int j = tid; j < HDIM * 16; j += blockDim.x) W16s[j] = W16[j];
        if (tid < 16) b16s[tid] = b16[tid];
    }
    if (tid < HDIM) bsm[tid] = bcur[tid];
    __syncthreads();

    const float* __restrict__ hp_in  = pp ? g_hpB : g_hpA;
    float*       __restrict__ hp_out = pp ? g_hpA : g_hpB;
    const float* __restrict__ pl_in  = g_plbuf[pp];
    const float* __restrict__ pr_in  = g_prbuf[pp];
    float*       __restrict__ pl_out = g_plbuf[pp ^ 1];
    float*       __restrict__ pr_out = g_prbuf[pp ^ 1];

    int lane = tid & 31, w = tid >> 5;
    float* tw = tile[w];
    int wg = (blockIdx.x * blockDim.x + tid) >> 5;
    int nw = (gridDim.x * blockDim.x) >> 5;

    for (int i = wg; i < N; i += nw) {
        float4 hi4[8];
        const float4* hip = reinterpret_cast<const float4*>(hp_in + i * HDIM);
        #pragma unroll
        for (int q = 0; q < 8; q++) hi4[q] = hip[q];      // broadcast load, replicated per lane
        float pri = pr_in[i];
        int beg = g_rowptr[i], end = g_rowptr[i + 1];

        float m = -1e30f, den = 0.0f, acc = 0.0f;
        for (int c = beg; c < end; c += 32) {
            int  cnt   = min(32, end - c);
            bool valid = lane < cnt;
            int  s     = valid ? g_col[c + lane] : 0;
            float pls  = valid ? pl_in[s] : 0.0f;

            // stage 32 hj rows into smem (coalesced gmem, conflict-free smem)
            for (int e = 0; e < cnt; e++) {
                int se = __shfl_sync(FULLMASK, s, e);
                tw[e * 36 + lane] = hp_in[se * HDIM + lane];
            }
            __syncwarp();

            // per-lane dot(hi, hj_lane)
            float dot = 0.0f;
            const float4* tp = reinterpret_cast<const float4*>(tw + lane * 36);
            #pragma unroll
            for (int q = 0; q < 8; q++) {
                float4 v = tp[q], hv = hi4[q];
                dot = fmaf(v.x, hv.x, dot);
                dot = fmaf(v.y, hv.y, dot);
                dot = fmaf(v.z, hv.z, dot);
                dot = fmaf(v.w, hv.w, dot);
            }

            // alpha = leaky_relu((pl[src]+pr[dst]) * sigmoid(dot))
            float e1  = fexp(-fabsf(dot));
            float r   = rcp1p(e1);
            float sig = (dot >= 0.0f) ? r : 1.0f - r;
            float a   = (pls + pri) * sig;
            a = (a >= 0.0f) ? a : 0.2f * a;
            if (!valid) a = -1e30f;

            // chunk max + online softmax combine
            float cm = a;
            #pragma unroll
            for (int off = 16; off; off >>= 1) cm = fmaxf(cm, __shfl_xor_sync(FULLMASK, cm, off));
            float mnew  = fmaxf(m, cm);
            float wv    = valid ? fexp(a - mnew) : 0.0f;
            float ws    = wv;
            #pragma unroll
            for (int off = 16; off; off >>= 1) ws += __shfl_xor_sync(FULLMASK, ws, off);
            float scale = fexp(m - mnew);
            den = fmaf(den, scale, ws);
            acc *= scale;
            m = mnew;

            // aggregate: acc[lane] += sum_e w_e * hj_e[lane]
            for (int e = 0; e < cnt; e++) {
                float we = __shfl_sync(FULLMASK, wv, e);
                acc = fmaf(we, tw[e * 36 + lane], acc);
            }
            __syncwarp();
        }

        float o = fmaf(acc, __fdividef(1.0f, den), bsm[lane]);
        o = fmaxf(o, 0.0f);                               // relu(h_new)

        if (!last) {
            // fused: hp_next = h_new @ Wnext ; pl/pr projections
            float hv = 0.0f;
            #pragma unroll
            for (int k = 0; k < HDIM; k++) {
                float ok = __shfl_sync(FULLMASK, o, k);
                hv = fmaf(ok, Wns[k * HDIM + lane], hv);
            }
            hp_out[i * HDIM + lane] = hv;
            float t1 = hv * als[lane], t2 = hv * ars[lane];
            #pragma unroll
            for (int off = 16; off; off >>= 1) {
                t1 += __shfl_xor_sync(FULLMASK, t1, off);
                t2 += __shfl_xor_sync(FULLMASK, t2, off);
            }
            if (lane == 0) { pl_out[i] = t1; pr_out[i] = t2; }
        } else {
            // fused final: out = h_new @ W16 + b16
            float hv = 0.0f;
            #pragma unroll
            for (int k = 0; k < HDIM; k++) {
                float ok = __shfl_sync(FULLMASK, o, k);
                if (lane < 16) hv = fmaf(ok, W16s[k * 16 + lane], hv);
            }
            if (lane < 16) out16[i * 16 + lane] = hv + b16s[lane];
        }
    }
}

// ---------------- host ----------------
extern "C" void kernel_launch(void* const* d_in, const int* in_sizes, int n_in,
                              void* d_out, int out_size) {
    const float* x   = (const float*)d_in[0];
    const int*   ei  = (const int*)d_in[1];
    const float* W0  = (const float*)d_in[2];
    const float* b0  = (const float*)d_in[3];
    const float* Ws  = (const float*)d_in[4];   // [15,32,32]
    const float* al  = (const float*)d_in[5];   // [15,32]
    const float* ar  = (const float*)d_in[6];   // [15,32]
    const float* bs  = (const float*)d_in[7];   // [15,32]
    const float* W16 = (const float*)d_in[8];   // [32,16]
    const float* b16 = (const float*)d_in[9];   // [16]
    float* out = (float*)d_out;

    const int N = in_sizes[0] / 128;
    const int E = in_sizes[1] / 2;
    const int L = 15;

    // ---- CSR build ----
    k_deg_init<<<(N + 255) / 256, 256>>>(N);
    k_deg_count<<<(E + 255) / 256, 256>>>(ei, E);
    int nb = (N + 511) / 512;
    k_scan1<<<nb, 512>>>(N);
    k_scan2<<<1, 512>>>(nb);
    k_scan3<<<nb, 512>>>(N);
    k_scatter<<<(E + N + 255) / 256, 256>>>(ei, E, N);
    k_sort<<<(N + 127) / 128, 128>>>(N);

    // ---- input layer ----
    k_in<<<740, 256>>>(x, W0, b0, Ws, al, ar, N);

    // ---- 15 SuperGAT layers (fused next-layer GEMM in epilogue) ----
    for (int l = 0; l < L; l++) {
        int pp   = l & 1;
        int last = (l == L - 1);
        const float* bcur   = bs + l * 32;
        const float* Wnext  = last ? Ws : (Ws + (l + 1) * 32 * 32);
        const float* alnext = last ? al : (al + (l + 1) * 32);
        const float* arnext = last ? ar : (ar + (l + 1) * 32);
        k_edge<<<740, 256>>>(pp, bcur, Wnext, alnext, arnext, W16, b16, out, N, last);
    }
}

// round 3
// speedup vs baseline: 1.7995x; 1.7995x over previous
#include <cuda_runtime.h>

#define FULLMASK 0xffffffffu

constexpr int NMAX = 50000;
constexpr int EMAX = 850000;   // 800000 edges + 50000 self loops
constexpr int HDIM = 32;

// ---------------- scratch (device globals; no allocation) ----------------
__device__ float g_hpA[NMAX * HDIM];
__device__ float g_hpB[NMAX * HDIM];
__device__ float g_plbuf[2][NMAX];
__device__ float g_prbuf[2][NMAX];
__device__ int   g_deg[NMAX];
__device__ int   g_rowptr[NMAX + 1];
__device__ int   g_cursor[NMAX];
__device__ int   g_col[EMAX];
__device__ int   g_bsum[512];

// ---------------- fast math (no MUFU) ----------------
// exp(x) for x <= 0 (clamped at -87). rel err ~1e-7.
__device__ __forceinline__ float fexp(float x) {
    x = fmaxf(x, -87.0f);
    float t = x * 1.4426950408889634f;       // log2(e)
    float r2 = t + 12582912.0f;              // round-to-nearest via magic number
    int   n  = __float_as_int(r2) - 0x4B400000;
    float f  = t - (r2 - 12582912.0f);       // f in [-0.5, 0.5]
    float p  = 1.5398530e-4f;
    p = fmaf(p, f, 1.3333558e-3f);
    p = fmaf(p, f, 9.6181291e-3f);
    p = fmaf(p, f, 5.5504109e-2f);
    p = fmaf(p, f, 2.4022651e-1f);
    p = fmaf(p, f, 6.9314718e-1f);
    p = fmaf(p, f, 1.0f);
    float s = __int_as_float((n + 127) << 23);
    return p * s;
}

// 1/(1+e) for e in [0,1]  (denominator d in (1,2]).
// Minimax linear seed 24/17 - 8/17*d, two Newton steps -> rel err ~1e-5.
__device__ __forceinline__ float rcp1p(float e) {
    float d = 1.0f + e;
    float y = fmaf(d, -0.47058824f, 1.41176471f);
    y = y * fmaf(-d, y, 2.0f);
    y = y * fmaf(-d, y, 2.0f);
    return y;
}

// ---------------- CSR build ----------------
__global__ void k_deg_init(int N) {
    int i = blockIdx.x * blockDim.x + threadIdx.x;
    if (i < N) g_deg[i] = 1;                 // self loop
}

__global__ void k_deg_count(const int* __restrict__ ei, int E) {
    int e = blockIdx.x * blockDim.x + threadIdx.x;
    if (e < E) atomicAdd(&g_deg[ei[E + e]], 1);
}

__global__ void k_scan1(int N) {
    __shared__ int sm[512];
    int i = blockIdx.x * 512 + threadIdx.x;
    int v = (i < N) ? g_deg[i] : 0;
    sm[threadIdx.x] = v;
    __syncthreads();
    #pragma unroll
    for (int off = 1; off < 512; off <<= 1) {
        int t = (threadIdx.x >= off) ? sm[threadIdx.x - off] : 0;
        __syncthreads();
        sm[threadIdx.x] += t;
        __syncthreads();
    }
    if (i < N) g_cursor[i] = sm[threadIdx.x];
    if (threadIdx.x == 511) g_bsum[blockIdx.x] = sm[511];
}

__global__ void k_scan2(int nb) {
    __shared__ int sm[512];
    if (threadIdx.x < nb) sm[threadIdx.x] = g_bsum[threadIdx.x];
    __syncthreads();
    if (threadIdx.x == 0) {
        int run = 0;
        for (int b = 0; b < nb; b++) { int t = sm[b]; sm[b] = run; run += t; }
    }
    __syncthreads();
    if (threadIdx.x < nb) g_bsum[threadIdx.x] = sm[threadIdx.x];
}

__global__ void k_scan3(int N) {
    int i = blockIdx.x * 512 + threadIdx.x;
    if (i < N) {
        int incl = g_cursor[i] + g_bsum[blockIdx.x];
        int excl = incl - g_deg[i];
        g_rowptr[i] = excl;
        g_cursor[i] = excl;
        if (i == N - 1) g_rowptr[N] = incl;
    }
}

__global__ void k_scatter(const int* __restrict__ ei, int E, int N) {
    int e = blockIdx.x * blockDim.x + threadIdx.x;
    if (e >= E + N) return;
    int s, d;
    if (e < E) { s = ei[e]; d = ei[E + e]; }
    else       { s = e - E; d = s; }
    int pos = atomicAdd(&g_cursor[d], 1);
    g_col[pos] = s;
}

// Warp-per-node bitonic sort (deg<=32: registers+shfl; rare deg>32: scalar fallback)
__global__ void k_sort(int N) {
    int warp = (blockIdx.x * blockDim.x + threadIdx.x) >> 5;
    int lane = threadIdx.x & 31;
    if (warp >= N) return;
    int beg = g_rowptr[warp];
    int cnt = g_rowptr[warp + 1] - beg;
    if (cnt <= 1) return;
    if (cnt <= 32) {
        int v = (lane < cnt) ? g_col[beg + lane] : 0x7fffffff;
        #pragma unroll
        for (int k = 2; k <= 32; k <<= 1) {
            #pragma unroll
            for (int jj = k >> 1; jj > 0; jj >>= 1) {
                int p = __shfl_xor_sync(FULLMASK, v, jj);
                bool up = ((lane & k) == 0);
                bool keepmin = (((lane & jj) == 0) == up);
                v = keepmin ? min(v, p) : max(v, p);
            }
        }
        if (lane < cnt) g_col[beg + lane] = v;
    } else if (lane == 0) {
        for (int a = 1; a < cnt; a++) {
            int key = g_col[beg + a], b = a - 1;
            while (b >= 0 && g_col[beg + b] > key) { g_col[beg + b + 1] = g_col[beg + b]; b--; }
            g_col[beg + b + 1] = key;
        }
    }
}

// ---------------- input layer: h0 = x@W0 + b0; hp0 = h0@Ws[0]; pl/pr ----------------
__global__ void __launch_bounds__(256) k_in(
    const float* __restrict__ x, const float* __restrict__ W0, const float* __restrict__ b0,
    const float* __restrict__ Ws0, const float* __restrict__ al0, const float* __restrict__ ar0,
    int N)
{
    __shared__ float W0s[128 * HDIM];
    __shared__ float b0s[HDIM];
    __shared__ float Wns[HDIM * HDIM];
    __shared__ float als[HDIM], ars[HDIM];
    int tid = threadIdx.x;
    for (int j = tid; j < 128 * HDIM; j += blockDim.x) W0s[j] = W0[j];
    for (int j = tid; j < HDIM * HDIM; j += blockDim.x) Wns[j] = Ws0[j];
    if (tid < HDIM) { b0s[tid] = b0[tid]; als[tid] = al0[tid]; ars[tid] = ar0[tid]; }
    __syncthreads();

    int lane = tid & 31;
    int wg = (blockIdx.x * blockDim.x + tid) >> 5;
    int nw = (gridDim.x * blockDim.x) >> 5;
    for (int i = wg; i < N; i += nw) {
        float xv[4];
        #pragma unroll
        for (int j = 0; j < 4; j++) xv[j] = x[i * 128 + j * 32 + lane];
        float h = 0.0f;
        #pragma unroll
        for (int k = 0; k < 128; k++) {
            float xk = __shfl_sync(FULLMASK, xv[k >> 5], k & 31);
            h = fmaf(xk, W0s[k * HDIM + lane], h);
        }
        h += b0s[lane];
        float hv = 0.0f;
        #pragma unroll
        for (int k = 0; k < HDIM; k++) {
            float hk = __shfl_sync(FULLMASK, h, k);
            hv = fmaf(hk, Wns[k * HDIM + lane], hv);
        }
        g_hpA[i * HDIM + lane] = hv;
        float t1 = hv * als[lane], t2 = hv * ars[lane];
        #pragma unroll
        for (int off = 16; off; off >>= 1) {
            t1 += __shfl_xor_sync(FULLMASK, t1, off);
            t2 += __shfl_xor_sync(FULLMASK, t2, off);
        }
        if (lane == 0) { g_plbuf[0][i] = t1; g_prbuf[0][i] = t2; }
    }
}

// ---------------- edge layer ----------------
// Warp = 4 groups x 8 lanes. Group g handles edge 4t+g at iteration t;
// lane (g,j) owns float4 slice [4j..4j+3] of the 32-dim rows.
// Lane l=(g,j) keeps scalar softmax state for edge perm(l)=4j+g.
__global__ void __launch_bounds__(256) k_edge(
    int pp,
    const float* __restrict__ bcur,
    const float* __restrict__ Wnext,
    const float* __restrict__ alnext, const float* __restrict__ arnext,
    const float* __restrict__ W16, const float* __restrict__ b16,
    float* __restrict__ out16,
    int N, int last)
{
    __shared__ float Wns[HDIM * HDIM];
    __shared__ float W16s[HDIM * 16];
    __shared__ float als[HDIM], ars[HDIM], bsm[HDIM];
    __shared__ float b16s[16];

    int tid = threadIdx.x;
    if (!last) {
        for (int q = tid; q < HDIM * HDIM; q += blockDim.x) Wns[q] = Wnext[q];
        if (tid < HDIM) { als[tid] = alnext[tid]; ars[tid] = arnext[tid]; }
    } else {
        for (int q = tid; q < HDIM * 16; q += blockDim.x) W16s[q] = W16[q];
        if (tid < 16) b16s[tid] = b16[tid];
    }
    if (tid < HDIM) bsm[tid] = bcur[tid];
    __syncthreads();

    const float* __restrict__ hp_in  = pp ? g_hpB : g_hpA;
    float*       __restrict__ hp_out = pp ? g_hpA : g_hpB;
    const float* __restrict__ pl_in  = g_plbuf[pp];
    const float* __restrict__ pr_in  = g_prbuf[pp];
    float*       __restrict__ pl_out = g_plbuf[pp ^ 1];
    float*       __restrict__ pr_out = g_prbuf[pp ^ 1];

    int lane = tid & 31;
    int g = lane >> 3;          // group 0..3
    int j = lane & 7;           // slice 0..7
    int perm = 4 * j + g;       // this lane's edge-within-chunk
    int gb = lane & 24;         // g*8

    int wg = (blockIdx.x * blockDim.x + tid) >> 5;
    int nw = (gridDim.x * blockDim.x) >> 5;

    for (int i = wg; i < N; i += nw) {
        float4 hi4 = *reinterpret_cast<const float4*>(hp_in + i * HDIM + 4 * j);
        float pri = pr_in[i];
        int beg = g_rowptr[i], end = g_rowptr[i + 1];

        float m = -1e30f, den = 0.0f;
        float4 acc = make_float4(0.f, 0.f, 0.f, 0.f);

        for (int c = beg; c < end; c += 32) {
            int cnt = min(32, end - c);
            bool vld = perm < cnt;
            int s = vld ? g_col[c + perm] : 0;
            float pls = vld ? pl_in[s] : 0.0f;
            int tmax = (cnt + 3) >> 2;

            // ---- dot pass: 4 edges per iteration ----
            float dotv = 0.0f;
            for (int t = 0; t < tmax; t++) {
                int se = __shfl_sync(FULLMASK, s, gb + t);
                bool act = (4 * t + g) < cnt;
                float d = 0.0f;
                if (act) {
                    float4 hj = *reinterpret_cast<const float4*>(hp_in + se * HDIM + 4 * j);
                    d = hj.x * hi4.x;
                    d = fmaf(hj.y, hi4.y, d);
                    d = fmaf(hj.z, hi4.z, d);
                    d = fmaf(hj.w, hi4.w, d);
                }
                d += __shfl_xor_sync(FULLMASK, d, 4);
                d += __shfl_xor_sync(FULLMASK, d, 2);
                d += __shfl_xor_sync(FULLMASK, d, 1);
                if (j == t) dotv = d;
            }

            // ---- alpha = leaky_relu((pl+pr)*sigmoid(dot)) ----
            float e1  = fexp(-fabsf(dotv));
            float r   = rcp1p(e1);
            float sig = (dotv >= 0.0f) ? r : 1.0f - r;
            float a   = (pls + pri) * sig;
            a = (a >= 0.0f) ? a : 0.2f * a;
            if (!vld) a = -1e30f;

            // ---- online softmax combine ----
            float cm = a;
            #pragma unroll
            for (int off = 16; off; off >>= 1) cm = fmaxf(cm, __shfl_xor_sync(FULLMASK, cm, off));
            float mnew = fmaxf(m, cm);
            float wv = vld ? fexp(a - mnew) : 0.0f;
            float ws = wv;
            #pragma unroll
            for (int off = 16; off; off >>= 1) ws += __shfl_xor_sync(FULLMASK, ws, off);
            float scale = fexp(m - mnew);
            den = fmaf(den, scale, ws);
            acc.x *= scale; acc.y *= scale; acc.z *= scale; acc.w *= scale;
            m = mnew;

            // ---- aggregation pass (rows hot in L1 from dot pass) ----
            for (int t = 0; t < tmax; t++) {
                int se = __shfl_sync(FULLMASK, s, gb + t);
                float we = __shfl_sync(FULLMASK, wv, gb + t);
                bool act = (4 * t + g) < cnt;
                if (act) {
                    float4 hj = *reinterpret_cast<const float4*>(hp_in + se * HDIM + 4 * j);
                    acc.x = fmaf(we, hj.x, acc.x);
                    acc.y = fmaf(we, hj.y, acc.y);
                    acc.z = fmaf(we, hj.z, acc.z);
                    acc.w = fmaf(we, hj.w, acc.w);
                }
            }
        }

        // cross-group reduce (all lanes end with full aggregated slice for dims 4j..4j+3)
        #pragma unroll
        for (int off = 8; off <= 16; off <<= 1) {
            acc.x += __shfl_xor_sync(FULLMASK, acc.x, off);
            acc.y += __shfl_xor_sync(FULLMASK, acc.y, off);
            acc.z += __shfl_xor_sync(FULLMASK, acc.z, off);
            acc.w += __shfl_xor_sync(FULLMASK, acc.w, off);
        }
        float rden = __fdividef(1.0f, den);
        float4 b4 = *reinterpret_cast<const float4*>(bsm + 4 * j);
        float oc[4];
        oc[0] = fmaxf(fmaf(acc.x, rden, b4.x), 0.0f);
        oc[1] = fmaxf(fmaf(acc.y, rden, b4.y), 0.0f);
        oc[2] = fmaxf(fmaf(acc.z, rden, b4.z), 0.0f);
        oc[3] = fmaxf(fmaf(acc.w, rden, b4.w), 0.0f);

        if (!last) {
            // hp_next = o @ Wnext ; group g covers k in [8g, 8g+8)
            float4 hv = make_float4(0.f, 0.f, 0.f, 0.f);
            #pragma unroll
            for (int t = 0; t < 8; t++) {
                int k = 8 * g + t;
                int srcl = 2 * g + (t >> 2);       // lane j0=k>>2 in group 0 holds dim k
                float ok = __shfl_sync(FULLMASK, oc[t & 3], srcl);
                float4 w4 = *reinterpret_cast<const float4*>(Wns + k * HDIM + 4 * j);
                hv.x = fmaf(ok, w4.x, hv.x);
                hv.y = fmaf(ok, w4.y, hv.y);
                hv.z = fmaf(ok, w4.z, hv.z);
                hv.w = fmaf(ok, w4.w, hv.w);
            }
            #pragma unroll
            for (int off = 8; off <= 16; off <<= 1) {
                hv.x += __shfl_xor_sync(FULLMASK, hv.x, off);
                hv.y += __shfl_xor_sync(FULLMASK, hv.y, off);
                hv.z += __shfl_xor_sync(FULLMASK, hv.z, off);
                hv.w += __shfl_xor_sync(FULLMASK, hv.w, off);
            }
            if (g == 0) *reinterpret_cast<float4*>(hp_out + i * HDIM + 4 * j) = hv;

            float4 al4 = *reinterpret_cast<const float4*>(als + 4 * j);
            float4 ar4 = *reinterpret_cast<const float4*>(ars + 4 * j);
            float t1 = hv.x * al4.x; t1 = fmaf(hv.y, al4.y, t1); t1 = fmaf(hv.z, al4.z, t1); t1 = fmaf(hv.w, al4.w, t1);
            float t2 = hv.x * ar4.x; t2 = fmaf(hv.y, ar4.y, t2); t2 = fmaf(hv.z, ar4.z, t2); t2 = fmaf(hv.w, ar4.w, t2);
            #pragma unroll
            for (int off = 4; off; off >>= 1) {
                t1 += __shfl_xor_sync(FULLMASK, t1, off);
                t2 += __shfl_xor_sync(FULLMASK, t2, off);
            }
            if (lane == 0) { pl_out[i] = t1; pr_out[i] = t2; }
        } else {
            // out = o @ W16 + b16 (16 outputs); lanes j<4 own output slice 4j..4j+3
            float4 hv = make_float4(0.f, 0.f, 0.f, 0.f);
            #pragma unroll
            for (int t = 0; t < 8; t++) {
                int k = 8 * g + t;
                int srcl = 2 * g + (t >> 2);
                float ok = __shfl_sync(FULLMASK, oc[t & 3], srcl);
                if (j < 4) {
                    float4 w4 = *reinterpret_cast<const float4*>(W16s + k * 16 + 4 * j);
                    hv.x = fmaf(ok, w4.x, hv.x);
                    hv.y = fmaf(ok, w4.y, hv.y);
                    hv.z = fmaf(ok, w4.z, hv.z);
                    hv.w = fmaf(ok, w4.w, hv.w);
                }
            }
            #pragma unroll
            for (int off = 8; off <= 16; off <<= 1) {
                hv.x += __shfl_xor_sync(FULLMASK, hv.x, off);
                hv.y += __shfl_xor_sync(FULLMASK, hv.y, off);
                hv.z += __shfl_xor_sync(FULLMASK, hv.z, off);
                hv.w += __shfl_xor_sync(FULLMASK, hv.w, off);
            }
            if (g == 0 && j < 4) {
                float4 bb = *reinterpret_cast<const float4*>(b16s + 4 * j);
                hv.x += bb.x; hv.y += bb.y; hv.z += bb.z; hv.w += bb.w;
                *reinterpret_cast<float4*>(out16 + i * 16 + 4 * j) = hv;
            }
        }
    }
}

// ---------------- host ----------------
extern "C" void kernel_launch(void* const* d_in, const int* in_sizes, int n_in,
                              void* d_out, int out_size) {
    const float* x   = (const float*)d_in[0];
    const int*   ei  = (const int*)d_in[1];
    const float* W0  = (const float*)d_in[2];
    const float* b0  = (const float*)d_in[3];
    const float* Ws  = (const float*)d_in[4];
    const float* al  = (const float*)d_in[5];
    const float* ar  = (const float*)d_in[6];
    const float* bs  = (const float*)d_in[7];
    const float* W16 = (const float*)d_in[8];
    const float* b16 = (const float*)d_in[9];
    float* out = (float*)d_out;

    const int N = in_sizes[0] / 128;
    const int E = in_sizes[1] / 2;
    const int L = 15;

    // ---- CSR build ----
    k_deg_init<<<(N + 255) / 256, 256>>>(N);
    k_deg_count<<<(E + 255) / 256, 256>>>(ei, E);
    int nb = (N + 511) / 512;
    k_scan1<<<nb, 512>>>(N);
    k_scan2<<<1, 512>>>(nb);
    k_scan3<<<nb, 512>>>(N);
    k_scatter<<<(E + N + 255) / 256, 256>>>(ei, E, N);
    k_sort<<<(N * 32 + 255) / 256, 256>>>(N);

    // ---- input layer ----
    k_in<<<740, 256>>>(x, W0, b0, Ws, al, ar, N);

    // ---- 15 SuperGAT layers ----
    for (int l = 0; l < L; l++) {
        int pp   = l & 1;
        int last = (l == L - 1);
        const float* bcur   = bs + l * 32;
        const float* Wnext  = last ? Ws : (Ws + (l + 1) * 32 * 32);
        const float* alnext = last ? al : (al + (l + 1) * 32);
        const float* arnext = last ? ar : (ar + (l + 1) * 32);
        k_edge<<<740, 256>>>(pp, bcur, Wnext, alnext, arnext, W16, b16, out, N, last);
    }
}